// round 13
// baseline (speedup 1.0000x reference)
#include <cuda_runtime.h>
#include <cuda_fp16.h>
#include <math.h>
#include <stdint.h>

typedef uint32_t u32; typedef uint64_t u64;

#define S_LEN 4096
#define B_SZ  2
#define DM    1024
#define NH    16
#define DK    64
#define RAD   8
#define WINW  9
#define M_TOT (B_SZ * S_LEN)
#define QT    64

// ---------------- scratch (device globals: allocation-free) ----------------
__device__ __half g_Xhi[M_TOT * DM];                      // x -> fp16 rn, [m][k]
__device__ __half g_Ahi[M_TOT * DM];                      // attn out -> fp16 rn, [m][k]
__device__ __half g_Whi[4][DM * DM], g_Wlo[4][DM * DM];   // W^T hi/lo, [n][k]
__device__ float  g_QKV[3][M_TOT * DM];                   // Q,K,V fp32

// ---------------- fp16 2-term tensor-core GEMM ----------------
// C = Ahi[m][k] @ (Bhi+Blo)[n][k]^T, fp32 accumulate.
#define BM 128
#define BN 128
#define BK 64
#define NSTG 4
#define PLANE_B (128 * 128)          // bytes per plane per stage
#define STG_B   (3 * PLANE_B)        // Ahi,Bhi,Blo = 48 KB
#define DYN_SMEM (NSTG * STG_B)      // 192 KB

__device__ __forceinline__ void cp16(u32 dst, const void* src) {
    asm volatile("cp.async.cg.shared.global [%0], [%1], 16;" :: "r"(dst), "l"(src) : "memory");
}

#define LDMX4(r, addr)                                                        \
    asm volatile("ldmatrix.sync.aligned.m8n8.x4.shared.b16 {%0,%1,%2,%3}, [%4];" \
                 : "=r"((r)[0]), "=r"((r)[1]), "=r"((r)[2]), "=r"((r)[3])     \
                 : "r"(addr))

#define MMA16(c, a, b)                                                        \
    asm volatile("mma.sync.aligned.m16n8k16.row.col.f32.f16.f16.f32 "         \
                 "{%0,%1,%2,%3}, {%4,%5,%6,%7}, {%8,%9}, {%0,%1,%2,%3};"      \
                 : "+f"((c)[0]), "+f"((c)[1]), "+f"((c)[2]), "+f"((c)[3])     \
                 : "r"((a)[0]), "r"((a)[1]), "r"((a)[2]), "r"((a)[3]),        \
                   "r"((b)[0]), "r"((b)[1]))

// Fused over multiple weight matrices: which = blockIdx.x / nxb selects the
// weight planes (stride DM*DM) and the output buffer (stride M_TOT*DM).
__global__ __launch_bounds__(256, 1)
void gemm_fp16x2(const __half* __restrict__ Ahi,
                 const __half* __restrict__ WhiBase, const __half* __restrict__ WloBase,
                 float* __restrict__ CBase, int nxb) {
    extern __shared__ char smc[];
    const u32 s0 = (u32)__cvta_generic_to_shared(smc);
    const int tid = threadIdx.x, wid = tid >> 5, lane = tid & 31;
    const int wm = wid & 1, wn = wid >> 1;              // 2x4 warp grid: 64x32 per warp
    const int which = blockIdx.x / nxb;
    const int m0 = blockIdx.y * BM, n0 = (blockIdx.x % nxb) * BN;
    const int g = lane >> 2, tg = lane & 3;

    const __half* Bhi = WhiBase + (size_t)which * DM * DM;
    const __half* Blo = WloBase + (size_t)which * DM * DM;
    float* C = CBase + (size_t)which * M_TOT * DM;

    // cp.async plan (computed addresses, no per-unit arrays):
    // thread covers rows r0+32j (j=0..3) of each plane, chunk c, swizzle j-invariant.
    const int r0 = tid >> 3, c = tid & 7;
    const u32 cx = (u32)((c ^ (r0 & 7)) * 16);
    const u32 sA  = s0 + (u32)r0 * 128 + cx;
    const u32 sBh = sA + PLANE_B;
    const u32 sBl = sA + 2 * PLANE_B;
    const char* a_base  = (const char*)Ahi + ((size_t)(m0 + r0) * DM + c * 8) * 2;
    const char* bh_base = (const char*)Bhi + ((size_t)(n0 + r0) * DM + c * 8) * 2;
    const char* bl_base = (const char*)Blo + ((size_t)(n0 + r0) * DM + c * 8) * 2;

#define ISSUE(kidx) do {                                                      \
    u32 so = ((kidx) & (NSTG - 1)) * STG_B;                                   \
    const char* ak = a_base  + (size_t)(kidx) * 128;                          \
    const char* bk = bh_base + (size_t)(kidx) * 128;                          \
    const char* ck = bl_base + (size_t)(kidx) * 128;                          \
    _Pragma("unroll")                                                         \
    for (int j = 0; j < 4; j++) {                                             \
        cp16(sA  + so + j * 4096, ak + (size_t)j * (64 * DM));                \
        cp16(sBh + so + j * 4096, bk + (size_t)j * (64 * DM));                \
        cp16(sBl + so + j * 4096, ck + (size_t)j * (64 * DM));                \
    }                                                                         \
    asm volatile("cp.async.commit_group;" ::: "memory");                      \
} while (0)

    ISSUE(0); ISSUE(1); ISSUE(2);

    float acc[4][4][4];
#pragma unroll
    for (int i = 0; i < 4; i++)
#pragma unroll
        for (int j = 0; j < 4; j++)
#pragma unroll
            for (int q = 0; q < 4; q++) acc[i][j][q] = 0.f;

    const int NIT = DM / BK;                            // 16
    const int rsel = lane & 15, csel = lane >> 4;

    for (int it = 0; it < NIT; it++) {
        asm volatile("cp.async.wait_group 2;" ::: "memory");
        __syncthreads();                                // single sync per iter
        if (it + 3 < NIT) ISSUE(it + 3);                // writes slot (it-1)&3: safe post-sync
        else asm volatile("cp.async.commit_group;" ::: "memory");

        const u32 sb = s0 + (it & (NSTG - 1)) * STG_B;

#pragma unroll
        for (int j = 0; j < 4; j++) {                   // four k16 steps per BK=64
            u32 ahi[4][4], bhi[4][2], blo[4][2];
#pragma unroll
            for (int mt = 0; mt < 4; mt++) {
                int row = wm * 64 + mt * 16 + rsel;
                u32 ad = sb + row * 128 + (((2 * j + csel) ^ (row & 7)) * 16);
                LDMX4(ahi[mt], ad);
            }
#pragma unroll
            for (int np = 0; np < 2; np++) {            // each x4 covers two n8 tiles
                int row = wn * 32 + np * 16 + rsel;
                u32 bd = sb + PLANE_B + row * 128 + (((2 * j + csel) ^ (row & 7)) * 16);
                u32 r[4];
                LDMX4(r, bd);
                bhi[2*np][0] = r[0]; bhi[2*np+1][0] = r[1];
                bhi[2*np][1] = r[2]; bhi[2*np+1][1] = r[3];
                LDMX4(r, bd + PLANE_B);
                blo[2*np][0] = r[0]; blo[2*np+1][0] = r[1];
                blo[2*np][1] = r[2]; blo[2*np+1][1] = r[3];
            }
#pragma unroll
            for (int mt = 0; mt < 4; mt++)
#pragma unroll
                for (int nt = 0; nt < 4; nt++) {
                    MMA16(acc[mt][nt], ahi[mt], bhi[nt]);
                    MMA16(acc[mt][nt], ahi[mt], blo[nt]);
                }
        }
    }

#pragma unroll
    for (int mt = 0; mt < 4; mt++)
#pragma unroll
        for (int nt = 0; nt < 4; nt++) {
            int row = m0 + wm * 64 + mt * 16 + g;
            int col = n0 + wn * 32 + nt * 8 + 2 * tg;
            float* p = C + (size_t)row * DM + col;
            *(float2*)p = make_float2(acc[mt][nt][0], acc[mt][nt][1]);
            *(float2*)(p + 8 * DM) = make_float2(acc[mt][nt][2], acc[mt][nt][3]);
        }
#undef ISSUE
}

// ---------------- x convert: fp32 -> fp16 rn ----------------
__global__ void convert_x_k(const float* __restrict__ in, __half* __restrict__ hi) {
    int i = blockIdx.x * blockDim.x + threadIdx.x;
    float4 v = ((const float4*)in)[i];
    ((__half2*)hi)[2 * i]     = __halves2half2(__float2half_rn(v.x), __float2half_rn(v.y));
    ((__half2*)hi)[2 * i + 1] = __halves2half2(__float2half_rn(v.z), __float2half_rn(v.w));
}

// ---------------- W transpose + split (all 4 weights, grid.z) ----------------
__global__ void transpose_split_k(const float* __restrict__ W0, const float* __restrict__ W1,
                                  const float* __restrict__ W2, const float* __restrict__ W3,
                                  __half* __restrict__ hiB, __half* __restrict__ loB) {
    __shared__ float t[32][33];
    int z = blockIdx.z;
    const float* W = (z == 0) ? W0 : (z == 1) ? W1 : (z == 2) ? W2 : W3;
    __half* hi = hiB + (size_t)z * DM * DM;
    __half* lo = loB + (size_t)z * DM * DM;
    int bx = blockIdx.x * 32, by = blockIdx.y * 32;
    int x = threadIdx.x, y = threadIdx.y;
#pragma unroll
    for (int j = 0; j < 32; j += 8)
        t[y + j][x] = W[(size_t)(by + y + j) * DM + bx + x];
    __syncthreads();
#pragma unroll
    for (int j = 0; j < 32; j += 8) {
        float v = t[x][y + j];
        __half h = __float2half_rn(v);
        size_t o = (size_t)(bx + y + j) * DM + by + x;
        hi[o] = h;
        lo[o] = __float2half_rn(v - __half2float(h));
    }
}

// ---------------- windowed causal attention: register-resident K/V window ----------------
__global__ __launch_bounds__(256)
void attn_kernel(const float* __restrict__ Q, const float* __restrict__ K,
                 const float* __restrict__ V, __half* __restrict__ Ohi) {
    const int warp = threadIdx.x >> 5, lane = threadIdx.x & 31;
    const int h = blockIdx.y, b = blockIdx.z;
    const size_t bh = (size_t)b * S_LEN * DM + (size_t)h * DK;
    const int sl0 = blockIdx.x * QT + warp * 8;     // first query of this warp
    const float scale = 1.0f / 0.56f;               // 1/(2T), T=0.28

    // K/V rows sl0-8 .. sl0+7 (16 rows) in registers; coalesced LDG, L2 absorbs overlap.
    float kr[16][2], vr[16][2];
#pragma unroll
    for (int r = 0; r < 16; r++) {
        int j = sl0 - RAD + r;
        bool ok = (j >= 0);
        const float* kp = K + bh + (size_t)j * DM;
        const float* vp = V + bh + (size_t)j * DM;
        kr[r][0] = ok ? kp[lane] : 0.f;  kr[r][1] = ok ? kp[lane + 32] : 0.f;
        vr[r][0] = ok ? vp[lane] : 0.f;  vr[r][1] = ok ? vp[lane + 32] : 0.f;
    }

#pragma unroll
    for (int qi = 0; qi < 8; qi++) {
        int s = sl0 + qi;
        float q0 = Q[bh + (size_t)s * DM + lane];
        float q1 = Q[bh + (size_t)s * DM + lane + 32];

        float sc[WINW];
#pragma unroll
        for (int w = 0; w < WINW; w++) {
            int r = qi + w;                         // key position s-RAD+w
            float p = q0 * kr[r][0] + q1 * kr[r][1];
#pragma unroll
            for (int o = 16; o > 0; o >>= 1)
                p += __shfl_xor_sync(0xffffffffu, p, o);
            sc[w] = (s - RAD + w >= 0) ? p * scale : -INFINITY;
        }

        float m = sc[0];
#pragma unroll
        for (int w = 1; w < WINW; w++) m = fmaxf(m, sc[w]);

        float sum = 0.f, a0 = 0.f, a1 = 0.f;
#pragma unroll
        for (int w = 0; w < WINW; w++) {
            float e = __expf(sc[w] - m);
            sum += e;
            int r = qi + w;
            a0 += e * vr[r][0];
            a1 += e * vr[r][1];
        }
        float inv = 1.0f / sum;
        Ohi[bh + (size_t)s * DM + lane]      = __float2half_rn(a0 * inv);
        Ohi[bh + (size_t)s * DM + lane + 32] = __float2half_rn(a1 * inv);
    }
}

// ---------------- launch ----------------
extern "C" void kernel_launch(void* const* d_in, const int* in_sizes, int n_in,
                              void* d_out, int out_size) {
    const float* x  = (const float*)d_in[0];
    const float* Wq = (const float*)d_in[1];
    const float* Wk = (const float*)d_in[2];
    const float* Wv = (const float*)d_in[3];
    const float* Wo = (const float*)d_in[4];
    float* out = (float*)d_out;

    __half *pXhi, *pAhi, *pWhi, *pWlo;
    float *pQKV;
    cudaGetSymbolAddress((void**)&pXhi, g_Xhi);
    cudaGetSymbolAddress((void**)&pAhi, g_Ahi);
    cudaGetSymbolAddress((void**)&pWhi, g_Whi);
    cudaGetSymbolAddress((void**)&pWlo, g_Wlo);
    cudaGetSymbolAddress((void**)&pQKV, g_QKV);
    float* pQ = pQKV + 0 * (size_t)M_TOT * DM;
    float* pK = pQKV + 1 * (size_t)M_TOT * DM;
    float* pV = pQKV + 2 * (size_t)M_TOT * DM;

    cudaFuncSetAttribute(gemm_fp16x2, cudaFuncAttributeMaxDynamicSharedMemorySize, DYN_SMEM);

    convert_x_k<<<(M_TOT * DM / 4) / 256, 256>>>(x, pXhi);

    dim3 tg(DM / 32, DM / 32, 4), tb(32, 8);
    transpose_split_k<<<tg, tb>>>(Wq, Wk, Wv, Wo, pWhi, pWlo);

    // fused QKV: grid.x = 3 weights x 8 n-blocks
    dim3 gqkv(3 * (DM / BN), M_TOT / BM);
    gemm_fp16x2<<<gqkv, 256, DYN_SMEM>>>(pXhi, pWhi, pWlo, pQKV, DM / BN);

    dim3 ga(S_LEN / QT, NH, B_SZ);
    attn_kernel<<<ga, 256>>>(pQ, pK, pV, pAhi);

    // output projection: weight index 3
    dim3 go(DM / BN, M_TOT / BM);
    gemm_fp16x2<<<go, 256, DYN_SMEM>>>(pAhi, pWhi + 3 * (size_t)DM * DM,
                                       pWlo + 3 * (size_t)DM * DM, out, DM / BN);
}

// round 14
// speedup vs baseline: 1.0615x; 1.0615x over previous
#include <cuda_runtime.h>
#include <cuda_fp16.h>
#include <math.h>
#include <stdint.h>

typedef uint32_t u32; typedef uint64_t u64;

#define S_LEN 4096
#define B_SZ  2
#define DM    1024
#define NH    16
#define DK    64
#define RAD   8
#define WINW  9
#define M_TOT (B_SZ * S_LEN)
#define QT    64

// ---------------- scratch (device globals: allocation-free) ----------------
__device__ __half g_Xhi[M_TOT * DM];                      // x -> fp16 rn, [m][k]
__device__ __half g_Ahi[M_TOT * DM];                      // attn out -> fp16 rn, [m][k]
__device__ __half g_Whi[4][DM * DM], g_Wlo[4][DM * DM];   // W^T hi/lo, [n][k]
__device__ float  g_QKV[3][M_TOT * DM];                   // Q,K,V fp32

// ---------------- fp16 2-term tensor-core GEMM ----------------
// C = Ahi[m][k] @ (Bhi+Blo)[n][k]^T, fp32 accumulate.
// Tile: BM=256 x BN=128, warp tile 64x64 (4x2 warps) -> 5.3 MMA/ldmatrix,
// smem read traffic ~128 B/cyc (at crossbar budget, vs 172 at 64x32).
#define BM 256
#define BN 128
#define BK 64
#define NSTG 3
#define A_PL (BM * 128)              // 32 KB
#define B_PL (BN * 128)              // 16 KB per plane
#define STG_B (A_PL + 2 * B_PL)      // 64 KB
#define DYN_SMEM (NSTG * STG_B)      // 192 KB

__device__ __forceinline__ void cp16(u32 dst, const void* src) {
    asm volatile("cp.async.cg.shared.global [%0], [%1], 16;" :: "r"(dst), "l"(src) : "memory");
}

#define LDMX4(r, addr)                                                        \
    asm volatile("ldmatrix.sync.aligned.m8n8.x4.shared.b16 {%0,%1,%2,%3}, [%4];" \
                 : "=r"((r)[0]), "=r"((r)[1]), "=r"((r)[2]), "=r"((r)[3])     \
                 : "r"(addr))

#define MMA16(c, a, b)                                                        \
    asm volatile("mma.sync.aligned.m16n8k16.row.col.f32.f16.f16.f32 "         \
                 "{%0,%1,%2,%3}, {%4,%5,%6,%7}, {%8,%9}, {%0,%1,%2,%3};"      \
                 : "+f"((c)[0]), "+f"((c)[1]), "+f"((c)[2]), "+f"((c)[3])     \
                 : "r"((a)[0]), "r"((a)[1]), "r"((a)[2]), "r"((a)[3]),        \
                   "r"((b)[0]), "r"((b)[1]))

// which = blockIdx.x / nxb selects weight planes + output buffer.
__global__ __launch_bounds__(256, 1)
void gemm_fp16x2(const __half* __restrict__ Ahi,
                 const __half* __restrict__ WhiBase, const __half* __restrict__ WloBase,
                 float* __restrict__ CBase, int nxb) {
    extern __shared__ char smc[];
    const u32 s0 = (u32)__cvta_generic_to_shared(smc);
    const int tid = threadIdx.x, wid = tid >> 5, lane = tid & 31;
    const int wm = wid & 3, wn = wid >> 2;              // 4x2 warp grid: 64x64 per warp
    const int which = blockIdx.x / nxb;
    const int m0 = blockIdx.y * BM, n0 = (blockIdx.x % nxb) * BN;
    const int g = lane >> 2, tg = lane & 3;

    const __half* Bhi = WhiBase + (size_t)which * DM * DM;
    const __half* Blo = WloBase + (size_t)which * DM * DM;
    float* C = CBase + (size_t)which * M_TOT * DM;

    // cp.async: thread covers rows r0+32j; chunk c; swizzle j-invariant.
    const int r0 = tid >> 3, c = tid & 7;
    const u32 cx = (u32)((c ^ (r0 & 7)) * 16);
    const u32 sA  = s0 + (u32)r0 * 128 + cx;
    const u32 sBh = s0 + A_PL + (u32)r0 * 128 + cx;
    const u32 sBl = sBh + B_PL;
    const char* a_base  = (const char*)Ahi + ((size_t)(m0 + r0) * DM + c * 8) * 2;
    const char* bh_base = (const char*)Bhi + ((size_t)(n0 + r0) * DM + c * 8) * 2;
    const char* bl_base = (const char*)Blo + ((size_t)(n0 + r0) * DM + c * 8) * 2;

#define ISSUE(kidx) do {                                                      \
    u32 so = ((kidx) % NSTG) * STG_B;                                         \
    const char* ak = a_base  + (size_t)(kidx) * 128;                          \
    const char* bk = bh_base + (size_t)(kidx) * 128;                          \
    const char* ck = bl_base + (size_t)(kidx) * 128;                          \
    _Pragma("unroll")                                                         \
    for (int j = 0; j < 8; j++)                                               \
        cp16(sA + so + j * 4096, ak + (size_t)j * (64 * DM));                 \
    _Pragma("unroll")                                                         \
    for (int j = 0; j < 4; j++) {                                             \
        cp16(sBh + so + j * 4096, bk + (size_t)j * (64 * DM));                \
        cp16(sBl + so + j * 4096, ck + (size_t)j * (64 * DM));                \
    }                                                                         \
    asm volatile("cp.async.commit_group;" ::: "memory");                      \
} while (0)

    ISSUE(0); ISSUE(1);

    float acc[4][8][4];
#pragma unroll
    for (int i = 0; i < 4; i++)
#pragma unroll
        for (int j = 0; j < 8; j++)
#pragma unroll
            for (int q = 0; q < 4; q++) acc[i][j][q] = 0.f;

    const int NIT = DM / BK;                            // 16
    const int rsel = lane & 15, csel = lane >> 4;

    for (int it = 0; it < NIT; it++) {
        asm volatile("cp.async.wait_group 1;" ::: "memory");
        __syncthreads();                                // single sync per iter
        if (it + 2 < NIT) ISSUE(it + 2);                // writes slot (it-1)%3: safe post-sync
        else asm volatile("cp.async.commit_group;" ::: "memory");

        const u32 sb = s0 + (it % NSTG) * STG_B;

#pragma unroll
        for (int j = 0; j < 4; j++) {                   // four k16 steps per BK=64
            u32 a[4][4];
#pragma unroll
            for (int mt = 0; mt < 4; mt++) {
                int row = wm * 64 + mt * 16 + rsel;
                u32 ad = sb + row * 128 + (((2 * j + csel) ^ (row & 7)) * 16);
                LDMX4(a[mt], ad);
            }
#pragma unroll
            for (int np = 0; np < 4; np++) {            // n16 slab -> nt pair (2np, 2np+1)
                int row = wn * 64 + np * 16 + rsel;
                u32 bd = sb + A_PL + row * 128 + (((2 * j + csel) ^ (row & 7)) * 16);
                u32 rh[4], rl[4];
                LDMX4(rh, bd);
                LDMX4(rl, bd + B_PL);
                u32 bh0[2] = {rh[0], rh[2]}, bh1[2] = {rh[1], rh[3]};
                u32 bl0[2] = {rl[0], rl[2]}, bl1[2] = {rl[1], rl[3]};
#pragma unroll
                for (int mt = 0; mt < 4; mt++) {
                    MMA16(acc[mt][2 * np],     a[mt], bh0);
                    MMA16(acc[mt][2 * np],     a[mt], bl0);
                    MMA16(acc[mt][2 * np + 1], a[mt], bh1);
                    MMA16(acc[mt][2 * np + 1], a[mt], bl1);
                }
            }
        }
    }

#pragma unroll
    for (int mt = 0; mt < 4; mt++)
#pragma unroll
        for (int nt = 0; nt < 8; nt++) {
            int row = m0 + wm * 64 + mt * 16 + g;
            int col = n0 + wn * 64 + nt * 8 + 2 * tg;
            float* p = C + (size_t)row * DM + col;
            *(float2*)p = make_float2(acc[mt][nt][0], acc[mt][nt][1]);
            *(float2*)(p + 8 * DM) = make_float2(acc[mt][nt][2], acc[mt][nt][3]);
        }
#undef ISSUE
}

// ---------------- x convert: fp32 -> fp16 rn ----------------
__global__ void convert_x_k(const float* __restrict__ in, __half* __restrict__ hi) {
    int i = blockIdx.x * blockDim.x + threadIdx.x;
    float4 v = ((const float4*)in)[i];
    ((__half2*)hi)[2 * i]     = __halves2half2(__float2half_rn(v.x), __float2half_rn(v.y));
    ((__half2*)hi)[2 * i + 1] = __halves2half2(__float2half_rn(v.z), __float2half_rn(v.w));
}

// ---------------- W transpose + split (all 4 weights, grid.z) ----------------
__global__ void transpose_split_k(const float* __restrict__ W0, const float* __restrict__ W1,
                                  const float* __restrict__ W2, const float* __restrict__ W3,
                                  __half* __restrict__ hiB, __half* __restrict__ loB) {
    __shared__ float t[32][33];
    int z = blockIdx.z;
    const float* W = (z == 0) ? W0 : (z == 1) ? W1 : (z == 2) ? W2 : W3;
    __half* hi = hiB + (size_t)z * DM * DM;
    __half* lo = loB + (size_t)z * DM * DM;
    int bx = blockIdx.x * 32, by = blockIdx.y * 32;
    int x = threadIdx.x, y = threadIdx.y;
#pragma unroll
    for (int j = 0; j < 32; j += 8)
        t[y + j][x] = W[(size_t)(by + y + j) * DM + bx + x];
    __syncthreads();
#pragma unroll
    for (int j = 0; j < 32; j += 8) {
        float v = t[x][y + j];
        __half h = __float2half_rn(v);
        size_t o = (size_t)(bx + y + j) * DM + by + x;
        hi[o] = h;
        lo[o] = __float2half_rn(v - __half2float(h));
    }
}

// ---------------- windowed causal attention (smem-staged; round-8 form) ----------------
__global__ __launch_bounds__(256)
void attn_kernel(const float* __restrict__ Q, const float* __restrict__ K,
                 const float* __restrict__ V, __half* __restrict__ Ohi) {
    int qbase = blockIdx.x * QT;
    int h = blockIdx.y;
    int b = blockIdx.z;

    __shared__ __align__(16) float Ks[QT + RAD][DK];
    __shared__ __align__(16) float Vs[QT + RAD][DK];

    int tid = threadIdx.x;
    const size_t bh = (size_t)b * S_LEN * DM + (size_t)h * DK;
    int base = qbase - RAD;

    for (int idx = tid; idx < (QT + RAD) * (DK / 4); idx += blockDim.x) {
        int r = idx / (DK / 4);
        int cidx = (idx % (DK / 4)) * 4;
        int j = base + r;
        float4 kv = make_float4(0.f, 0.f, 0.f, 0.f), vv = kv;
        if (j >= 0) {
            kv = *(const float4*)(K + bh + (size_t)j * DM + cidx);
            vv = *(const float4*)(V + bh + (size_t)j * DM + cidx);
        }
        *(float4*)&Ks[r][cidx] = kv;
        *(float4*)&Vs[r][cidx] = vv;
    }
    __syncthreads();

    int warp = tid >> 5, lane = tid & 31;
    const float scale = 1.0f / 0.56f;   // 1/(2T), T=0.28

    for (int qi = 0; qi < QT / 8; qi++) {
        int sl = warp * (QT / 8) + qi;
        int s = qbase + sl;
        float q0 = Q[bh + (size_t)s * DM + lane];
        float q1 = Q[bh + (size_t)s * DM + lane + 32];

        float sc[WINW];
#pragma unroll
        for (int w = 0; w < WINW; w++) {
            int r = sl + w;
            float p = q0 * Ks[r][lane] + q1 * Ks[r][lane + 32];
#pragma unroll
            for (int o = 16; o > 0; o >>= 1)
                p += __shfl_xor_sync(0xffffffffu, p, o);
            sc[w] = (s - RAD + w >= 0) ? p * scale : -INFINITY;
        }

        float m = sc[0];
#pragma unroll
        for (int w = 1; w < WINW; w++) m = fmaxf(m, sc[w]);

        float sum = 0.f, a0 = 0.f, a1 = 0.f;
#pragma unroll
        for (int w = 0; w < WINW; w++) {
            float e = __expf(sc[w] - m);
            sum += e;
            int r = sl + w;
            a0 += e * Vs[r][lane];
            a1 += e * Vs[r][lane + 32];
        }
        float inv = 1.0f / sum;
        Ohi[bh + (size_t)s * DM + lane]      = __float2half_rn(a0 * inv);
        Ohi[bh + (size_t)s * DM + lane + 32] = __float2half_rn(a1 * inv);
    }
}

// ---------------- launch ----------------
extern "C" void kernel_launch(void* const* d_in, const int* in_sizes, int n_in,
                              void* d_out, int out_size) {
    const float* x  = (const float*)d_in[0];
    const float* Wq = (const float*)d_in[1];
    const float* Wk = (const float*)d_in[2];
    const float* Wv = (const float*)d_in[3];
    const float* Wo = (const float*)d_in[4];
    float* out = (float*)d_out;

    __half *pXhi, *pAhi, *pWhi, *pWlo;
    float *pQKV;
    cudaGetSymbolAddress((void**)&pXhi, g_Xhi);
    cudaGetSymbolAddress((void**)&pAhi, g_Ahi);
    cudaGetSymbolAddress((void**)&pWhi, g_Whi);
    cudaGetSymbolAddress((void**)&pWlo, g_Wlo);
    cudaGetSymbolAddress((void**)&pQKV, g_QKV);
    float* pQ = pQKV + 0 * (size_t)M_TOT * DM;
    float* pK = pQKV + 1 * (size_t)M_TOT * DM;
    float* pV = pQKV + 2 * (size_t)M_TOT * DM;

    cudaFuncSetAttribute(gemm_fp16x2, cudaFuncAttributeMaxDynamicSharedMemorySize, DYN_SMEM);

    convert_x_k<<<(M_TOT * DM / 4) / 256, 256>>>(x, pXhi);

    dim3 tg(DM / 32, DM / 32, 4), tb(32, 8);
    transpose_split_k<<<tg, tb>>>(Wq, Wk, Wv, Wo, pWhi, pWlo);

    // fused QKV: grid.x = 3 weights x 8 n-blocks
    dim3 gqkv(3 * (DM / BN), M_TOT / BM);
    gemm_fp16x2<<<gqkv, 256, DYN_SMEM>>>(pXhi, pWhi, pWlo, pQKV, DM / BN);

    dim3 ga(S_LEN / QT, NH, B_SZ);
    attn_kernel<<<ga, 256>>>(pQ, pK, pV, pAhi);

    // output projection: weight index 3
    dim3 go(DM / BN, M_TOT / BM);
    gemm_fp16x2<<<go, 256, DYN_SMEM>>>(pAhi, pWhi + 3 * (size_t)DM * DM,
                                       pWlo + 3 * (size_t)DM * DM, out, DM / BN);
}

// round 15
// speedup vs baseline: 1.1716x; 1.1036x over previous
#include <cuda_runtime.h>
#include <cuda_fp16.h>
#include <math.h>
#include <stdint.h>

typedef uint32_t u32; typedef uint64_t u64;

#define S_LEN 4096
#define B_SZ  2
#define DM    1024
#define NH    16
#define DK    64
#define RAD   8
#define WINW  9
#define M_TOT (B_SZ * S_LEN)
#define QT    64

// ---------------- scratch (device globals: allocation-free) ----------------
__device__ __half g_Xhi[M_TOT * DM];                      // x -> fp16 rn, [m][k]
__device__ __half g_Ahi[M_TOT * DM];                      // attn out -> fp16 rn, [m][k]
__device__ __half g_Whi[4][DM * DM], g_Wlo[4][DM * DM];   // W^T hi/lo, [n][k]
__device__ float  g_QKV[3][M_TOT * DM];                   // Q,K,V fp32

// ---------------- fp16 2-term tensor-core GEMM ----------------
// C = Ahi[m][k] @ (Bhi+Blo)[n][k]^T, fp32 accumulate.
// 2 CTAs/SM (4 warps/SMSP) to hide ldmatrix/MMA latency; hi/lo MMAs spaced
// 16 apart to break accumulator RAW chains.
#define BM 128
#define BN 128
#define BK 64
#define NSTG 2
#define PLANE_B (128 * 128)          // 16 KB per plane per stage
#define STG_B   (3 * PLANE_B)        // 48 KB
#define DYN_SMEM (NSTG * STG_B)      // 96 KB -> 2 CTAs/SM

__device__ __forceinline__ void cp16(u32 dst, const void* src) {
    asm volatile("cp.async.cg.shared.global [%0], [%1], 16;" :: "r"(dst), "l"(src) : "memory");
}

#define LDMX4(r, addr)                                                        \
    asm volatile("ldmatrix.sync.aligned.m8n8.x4.shared.b16 {%0,%1,%2,%3}, [%4];" \
                 : "=r"((r)[0]), "=r"((r)[1]), "=r"((r)[2]), "=r"((r)[3])     \
                 : "r"(addr))

#define MMA16(c, a, b)                                                        \
    asm volatile("mma.sync.aligned.m16n8k16.row.col.f32.f16.f16.f32 "         \
                 "{%0,%1,%2,%3}, {%4,%5,%6,%7}, {%8,%9}, {%0,%1,%2,%3};"      \
                 : "+f"((c)[0]), "+f"((c)[1]), "+f"((c)[2]), "+f"((c)[3])     \
                 : "r"((a)[0]), "r"((a)[1]), "r"((a)[2]), "r"((a)[3]),        \
                   "r"((b)[0]), "r"((b)[1]))

// which = blockIdx.x / nxb selects weight planes + output buffer.
__global__ __launch_bounds__(256, 2)
void gemm_fp16x2(const __half* __restrict__ Ahi,
                 const __half* __restrict__ WhiBase, const __half* __restrict__ WloBase,
                 float* __restrict__ CBase, int nxb) {
    extern __shared__ char smc[];
    const u32 s0 = (u32)__cvta_generic_to_shared(smc);
    const int tid = threadIdx.x, wid = tid >> 5, lane = tid & 31;
    const int wm = wid & 1, wn = wid >> 1;              // 2x4 warp grid: 64x32 per warp
    const int which = blockIdx.x / nxb;
    const int m0 = blockIdx.y * BM, n0 = (blockIdx.x % nxb) * BN;
    const int g = lane >> 2, tg = lane & 3;

    const __half* Bhi = WhiBase + (size_t)which * DM * DM;
    const __half* Blo = WloBase + (size_t)which * DM * DM;
    float* C = CBase + (size_t)which * M_TOT * DM;

    // cp.async: thread covers rows r0+32j (j=0..3) per plane; swizzle j-invariant.
    const int r0 = tid >> 3, c = tid & 7;
    const u32 cx = (u32)((c ^ (r0 & 7)) * 16);
    const u32 sA  = s0 + (u32)r0 * 128 + cx;
    const u32 sBh = sA + PLANE_B;
    const u32 sBl = sA + 2 * PLANE_B;
    const char* a_base  = (const char*)Ahi + ((size_t)(m0 + r0) * DM + c * 8) * 2;
    const char* bh_base = (const char*)Bhi + ((size_t)(n0 + r0) * DM + c * 8) * 2;
    const char* bl_base = (const char*)Blo + ((size_t)(n0 + r0) * DM + c * 8) * 2;

#define ISSUE(kidx) do {                                                      \
    u32 so = ((kidx) & 1) * STG_B;                                            \
    const char* ak = a_base  + (size_t)(kidx) * 128;                          \
    const char* bk = bh_base + (size_t)(kidx) * 128;                          \
    const char* ck = bl_base + (size_t)(kidx) * 128;                          \
    _Pragma("unroll")                                                         \
    for (int j = 0; j < 4; j++) {                                             \
        cp16(sA  + so + j * 4096, ak + (size_t)j * (64 * DM));                \
        cp16(sBh + so + j * 4096, bk + (size_t)j * (64 * DM));                \
        cp16(sBl + so + j * 4096, ck + (size_t)j * (64 * DM));                \
    }                                                                         \
    asm volatile("cp.async.commit_group;" ::: "memory");                      \
} while (0)

    ISSUE(0);

    float acc[4][4][4];
#pragma unroll
    for (int i = 0; i < 4; i++)
#pragma unroll
        for (int j = 0; j < 4; j++)
#pragma unroll
            for (int q = 0; q < 4; q++) acc[i][j][q] = 0.f;

    const int NIT = DM / BK;                            // 16
    const int rsel = lane & 15, csel = lane >> 4;

    for (int it = 0; it < NIT; it++) {
        if (it + 1 < NIT) {
            ISSUE(it + 1);                              // into slot (it+1)&1 (not being read)
            asm volatile("cp.async.wait_group 1;" ::: "memory");
        } else {
            asm volatile("cp.async.wait_group 0;" ::: "memory");
        }
        __syncthreads();

        const u32 sb = s0 + (it & 1) * STG_B;

#pragma unroll
        for (int j = 0; j < 4; j++) {                   // four k16 steps per BK=64
            u32 ahi[4][4], bhi[4][2], blo[4][2];
#pragma unroll
            for (int mt = 0; mt < 4; mt++) {
                int row = wm * 64 + mt * 16 + rsel;
                u32 ad = sb + row * 128 + (((2 * j + csel) ^ (row & 7)) * 16);
                LDMX4(ahi[mt], ad);
            }
#pragma unroll
            for (int np = 0; np < 2; np++) {            // each x4 covers two n8 tiles
                int row = wn * 32 + np * 16 + rsel;
                u32 bd = sb + PLANE_B + row * 128 + (((2 * j + csel) ^ (row & 7)) * 16);
                u32 r[4];
                LDMX4(r, bd);
                bhi[2*np][0] = r[0]; bhi[2*np+1][0] = r[1];
                bhi[2*np][1] = r[2]; bhi[2*np+1][1] = r[3];
                LDMX4(r, bd + PLANE_B);
                blo[2*np][0] = r[0]; blo[2*np+1][0] = r[1];
                blo[2*np][1] = r[2]; blo[2*np+1][1] = r[3];
            }
            // hi phase then lo phase: RAW spacing on each acc = 16 MMAs,
            // per-acc add order (hi before lo) unchanged -> bitwise identical.
#pragma unroll
            for (int mt = 0; mt < 4; mt++)
#pragma unroll
                for (int nt = 0; nt < 4; nt++)
                    MMA16(acc[mt][nt], ahi[mt], bhi[nt]);
#pragma unroll
            for (int mt = 0; mt < 4; mt++)
#pragma unroll
                for (int nt = 0; nt < 4; nt++)
                    MMA16(acc[mt][nt], ahi[mt], blo[nt]);
        }
        __syncthreads();                                // slot reusable for ISSUE(it+2)
    }

#pragma unroll
    for (int mt = 0; mt < 4; mt++)
#pragma unroll
        for (int nt = 0; nt < 4; nt++) {
            int row = m0 + wm * 64 + mt * 16 + g;
            int col = n0 + wn * 32 + nt * 8 + 2 * tg;
            float* p = C + (size_t)row * DM + col;
            *(float2*)p = make_float2(acc[mt][nt][0], acc[mt][nt][1]);
            *(float2*)(p + 8 * DM) = make_float2(acc[mt][nt][2], acc[mt][nt][3]);
        }
#undef ISSUE
}

// ---------------- x convert: fp32 -> fp16 rn ----------------
__global__ void convert_x_k(const float* __restrict__ in, __half* __restrict__ hi) {
    int i = blockIdx.x * blockDim.x + threadIdx.x;
    float4 v = ((const float4*)in)[i];
    ((__half2*)hi)[2 * i]     = __halves2half2(__float2half_rn(v.x), __float2half_rn(v.y));
    ((__half2*)hi)[2 * i + 1] = __halves2half2(__float2half_rn(v.z), __float2half_rn(v.w));
}

// ---------------- W transpose + split (all 4 weights, grid.z) ----------------
__global__ void transpose_split_k(const float* __restrict__ W0, const float* __restrict__ W1,
                                  const float* __restrict__ W2, const float* __restrict__ W3,
                                  __half* __restrict__ hiB, __half* __restrict__ loB) {
    __shared__ float t[32][33];
    int z = blockIdx.z;
    const float* W = (z == 0) ? W0 : (z == 1) ? W1 : (z == 2) ? W2 : W3;
    __half* hi = hiB + (size_t)z * DM * DM;
    __half* lo = loB + (size_t)z * DM * DM;
    int bx = blockIdx.x * 32, by = blockIdx.y * 32;
    int x = threadIdx.x, y = threadIdx.y;
#pragma unroll
    for (int j = 0; j < 32; j += 8)
        t[y + j][x] = W[(size_t)(by + y + j) * DM + bx + x];
    __syncthreads();
#pragma unroll
    for (int j = 0; j < 32; j += 8) {
        float v = t[x][y + j];
        __half h = __float2half_rn(v);
        size_t o = (size_t)(bx + y + j) * DM + by + x;
        hi[o] = h;
        lo[o] = __float2half_rn(v - __half2float(h));
    }
}

// ---------------- windowed causal attention (smem-staged) ----------------
__global__ __launch_bounds__(256)
void attn_kernel(const float* __restrict__ Q, const float* __restrict__ K,
                 const float* __restrict__ V, __half* __restrict__ Ohi) {
    int qbase = blockIdx.x * QT;
    int h = blockIdx.y;
    int b = blockIdx.z;

    __shared__ __align__(16) float Ks[QT + RAD][DK];
    __shared__ __align__(16) float Vs[QT + RAD][DK];

    int tid = threadIdx.x;
    const size_t bh = (size_t)b * S_LEN * DM + (size_t)h * DK;
    int base = qbase - RAD;

    for (int idx = tid; idx < (QT + RAD) * (DK / 4); idx += blockDim.x) {
        int r = idx / (DK / 4);
        int cidx = (idx % (DK / 4)) * 4;
        int j = base + r;
        float4 kv = make_float4(0.f, 0.f, 0.f, 0.f), vv = kv;
        if (j >= 0) {
            kv = *(const float4*)(K + bh + (size_t)j * DM + cidx);
            vv = *(const float4*)(V + bh + (size_t)j * DM + cidx);
        }
        *(float4*)&Ks[r][cidx] = kv;
        *(float4*)&Vs[r][cidx] = vv;
    }
    __syncthreads();

    int warp = tid >> 5, lane = tid & 31;
    const float scale = 1.0f / 0.56f;   // 1/(2T), T=0.28

    for (int qi = 0; qi < QT / 8; qi++) {
        int sl = warp * (QT / 8) + qi;
        int s = qbase + sl;
        float q0 = Q[bh + (size_t)s * DM + lane];
        float q1 = Q[bh + (size_t)s * DM + lane + 32];

        float sc[WINW];
#pragma unroll
        for (int w = 0; w < WINW; w++) {
            int r = sl + w;
            float p = q0 * Ks[r][lane] + q1 * Ks[r][lane + 32];
#pragma unroll
            for (int o = 16; o > 0; o >>= 1)
                p += __shfl_xor_sync(0xffffffffu, p, o);
            sc[w] = (s - RAD + w >= 0) ? p * scale : -INFINITY;
        }

        float m = sc[0];
#pragma unroll
        for (int w = 1; w < WINW; w++) m = fmaxf(m, sc[w]);

        float sum = 0.f, a0 = 0.f, a1 = 0.f;
#pragma unroll
        for (int w = 0; w < WINW; w++) {
            float e = __expf(sc[w] - m);
            sum += e;
            int r = sl + w;
            a0 += e * Vs[r][lane];
            a1 += e * Vs[r][lane + 32];
        }
        float inv = 1.0f / sum;
        Ohi[bh + (size_t)s * DM + lane]      = __float2half_rn(a0 * inv);
        Ohi[bh + (size_t)s * DM + lane + 32] = __float2half_rn(a1 * inv);
    }
}

// ---------------- launch ----------------
extern "C" void kernel_launch(void* const* d_in, const int* in_sizes, int n_in,
                              void* d_out, int out_size) {
    const float* x  = (const float*)d_in[0];
    const float* Wq = (const float*)d_in[1];
    const float* Wk = (const float*)d_in[2];
    const float* Wv = (const float*)d_in[3];
    const float* Wo = (const float*)d_in[4];
    float* out = (float*)d_out;

    __half *pXhi, *pAhi, *pWhi, *pWlo;
    float *pQKV;
    cudaGetSymbolAddress((void**)&pXhi, g_Xhi);
    cudaGetSymbolAddress((void**)&pAhi, g_Ahi);
    cudaGetSymbolAddress((void**)&pWhi, g_Whi);
    cudaGetSymbolAddress((void**)&pWlo, g_Wlo);
    cudaGetSymbolAddress((void**)&pQKV, g_QKV);
    float* pQ = pQKV + 0 * (size_t)M_TOT * DM;
    float* pK = pQKV + 1 * (size_t)M_TOT * DM;
    float* pV = pQKV + 2 * (size_t)M_TOT * DM;

    cudaFuncSetAttribute(gemm_fp16x2, cudaFuncAttributeMaxDynamicSharedMemorySize, DYN_SMEM);

    convert_x_k<<<(M_TOT * DM / 4) / 256, 256>>>(x, pXhi);

    dim3 tg(DM / 32, DM / 32, 4), tb(32, 8);
    transpose_split_k<<<tg, tb>>>(Wq, Wk, Wv, Wo, pWhi, pWlo);

    // fused QKV: grid.x = 3 weights x 8 n-blocks
    dim3 gqkv(3 * (DM / BN), M_TOT / BM);
    gemm_fp16x2<<<gqkv, 256, DYN_SMEM>>>(pXhi, pWhi, pWlo, pQKV, DM / BN);

    dim3 ga(S_LEN / QT, NH, B_SZ);
    attn_kernel<<<ga, 256>>>(pQ, pK, pV, pAhi);

    // output projection: weight index 3
    dim3 go(DM / BN, M_TOT / BM);
    gemm_fp16x2<<<go, 256, DYN_SMEM>>>(pAhi, pWhi + 3 * (size_t)DM * DM,
                                       pWlo + 3 * (size_t)DM * DM, out, DM / BN);
}